// round 14
// baseline (speedup 1.0000x reference)
#include <cuda_runtime.h>

#define NIMG 96
#define HH 512
#define WW 512
#define HS 256   // cA resolution
#define WS 256

typedef unsigned long long ull;

__device__ __forceinline__ ull pk2(float lo, float hi) {
    ull r; asm("mov.b64 %0, {%1, %2};" : "=l"(r) : "f"(lo), "f"(hi)); return r;
}
__device__ __forceinline__ void upk2(ull v, float& lo, float& hi) {
    asm("mov.b64 {%0, %1}, %2;" : "=f"(lo), "=f"(hi) : "l"(v));
}
__device__ __forceinline__ void fma2(ull& d, ull a, ull b) {
    asm("fma.rn.f32x2 %0, %1, %2, %0;" : "+l"(d) : "l"(a), "l"(b));
}

// ---------------------------------------------------------------------------
// conv1 pair stage, WARP-PRIVATE: warp (wx,wy) computes its own 10x18 s1
// region (2 channels in f32x2 lanes), 2-wide tasks over a 10x9 task grid.
// 90 tasks / 32 lanes = 3 slots — same effective cost as the old block-wide
// version, but no block barrier needed afterwards.
// ---------------------------------------------------------------------------
__device__ __forceinline__ void conv1_pair_w(
    const float (*cAt)[72], float (*d0)[24], float (*d1)[24],
    const ull* __restrict__ wqs, float2 bias2,
    int lane, int wx, int wy, int r0s, int c0s, bool interior)
{
    ull wq[9];
    {   // wqs is 16B-aligned (stride-10 rows in w1p)
        ulonglong2 a = *(const ulonglong2*)(wqs);
        ulonglong2 b = *(const ulonglong2*)(wqs + 2);
        ulonglong2 c = *(const ulonglong2*)(wqs + 4);
        ulonglong2 d = *(const ulonglong2*)(wqs + 6);
        wq[0] = a.x; wq[1] = a.y; wq[2] = b.x; wq[3] = b.y;
        wq[4] = c.x; wq[5] = c.y; wq[6] = d.x; wq[7] = d.y;
        wq[8] = wqs[8];
    }

    int r = lane / 9, cp = lane - 9 * (lane / 9);
    for (int k = lane; k < 90; k += 32) {
        // cAt rows 16wy+2r .. +3, cols 32wx+4cp .. +5 (float4 base 16B aligned)
        const float* base = &cAt[16 * wy + 2 * r][32 * wx + 4 * cp];

        ull a[2][4];
#pragma unroll
        for (int j = 0; j < 2; j++)
#pragma unroll
            for (int q = 0; q < 4; q++) a[j][q] = 0ull;

#pragma unroll
        for (int i = 0; i < 4; i++) {              // input row offset i
            float4 q0 = *(const float4*)(base + i * 72);
            float2 q1 = *(const float2*)(base + i * 72 + 4);
            ull bb[6];
            bb[0] = pk2(q0.x, q0.x); bb[1] = pk2(q0.y, q0.y);
            bb[2] = pk2(q0.z, q0.z); bb[3] = pk2(q0.w, q0.w);
            bb[4] = pk2(q1.x, q1.x); bb[5] = pk2(q1.y, q1.y);
            if (i < 3) {                            // ky = i -> dy = 0
#pragma unroll
                for (int kx = 0; kx < 3; kx++) {
                    ull w = wq[3 * i + kx];
                    fma2(a[0][0], w, bb[kx]);
                    fma2(a[0][1], w, bb[kx + 1]);
                    fma2(a[1][0], w, bb[kx + 2]);
                    fma2(a[1][1], w, bb[kx + 3]);
                }
            }
            if (i > 0) {                            // ky = i-1 -> dy = 1
#pragma unroll
                for (int kx = 0; kx < 3; kx++) {
                    ull w = wq[3 * (i - 1) + kx];
                    fma2(a[0][2], w, bb[kx]);
                    fma2(a[0][3], w, bb[kx + 1]);
                    fma2(a[1][2], w, bb[kx + 2]);
                    fma2(a[1][3], w, bb[kx + 3]);
                }
            }
        }

        float2 o0, o1;
#pragma unroll
        for (int j = 0; j < 2; j++) {
            float l0, h0, l1, h1, l2, h2, l3, h3;
            upk2(a[j][0], l0, h0); upk2(a[j][1], l1, h1);
            upk2(a[j][2], l2, h2); upk2(a[j][3], l3, h3);
            float m0 = fmaxf(fmaxf(l0, l1), fmaxf(l2, l3));
            float m1 = fmaxf(fmaxf(h0, h1), fmaxf(h2, h3));
            m0 = fmaxf(m0 + bias2.x, 0.f);   // max(relu(x+b)) == relu(max+b)
            m1 = fmaxf(m1 + bias2.y, 0.f);
            if (!interior) {
                int rs = r0s + 8 * wy + r;             // global s1 row
                int cs = c0s + 16 * wx + 2 * cp + j;   // global s1 col
                if ((unsigned)rs >= 128u || (unsigned)cs >= 128u) { m0 = 0.f; m1 = 0.f; }
            }
            ((float*)&o0)[j] = m0;
            ((float*)&o1)[j] = m1;
        }
        *(float2*)&d0[r][2 * cp] = o0;
        *(float2*)&d1[r][2 * cp] = o1;

        cp += 5; r += 3;                 // advance 32 = 3*9 + 5
        if (cp >= 9) { cp -= 9; r++; }
    }
}

// ---------------------------------------------------------------------------
// conv2 stage, WARP-PRIVATE: accumulate one input channel from the warp's
// own 10x24 s1 buffer. Rolling 2-row broadcast buffer; oc-pairs in f32x2.
// Stride 24 floats -> row delta 48 words == 16 mod 32: conflict-free phases.
// ---------------------------------------------------------------------------
__device__ __forceinline__ void conv2_stage_w(
    const float (*src)[24], const ull* __restrict__ wrow,
    int lx, int ly, ull acc[4][4])
{
    ull rA[4], rB[4];
    {
        float2 v0 = *(const float2*)&src[2 * ly][2 * lx];
        float2 v1 = *(const float2*)&src[2 * ly][2 * lx + 2];
        rA[0] = pk2(v0.x, v0.x); rA[1] = pk2(v0.y, v0.y);
        rA[2] = pk2(v1.x, v1.x); rA[3] = pk2(v1.y, v1.y);
    }
#pragma unroll
    for (int ky = 0; ky < 3; ky++) {
        ull* top = (ky & 1) ? rB : rA;
        ull* bot = (ky & 1) ? rA : rB;
        {
            float2 v0 = *(const float2*)&src[2 * ly + ky + 1][2 * lx];
            float2 v1 = *(const float2*)&src[2 * ly + ky + 1][2 * lx + 2];
            bot[0] = pk2(v0.x, v0.x); bot[1] = pk2(v0.y, v0.y);
            bot[2] = pk2(v1.x, v1.x); bot[3] = pk2(v1.y, v1.y);
        }
#pragma unroll
        for (int kx = 0; kx < 3; kx++) {
            ulonglong2 wa = *(const ulonglong2*)&wrow[(ky * 3 + kx) * 4];
            ulonglong2 wb = *(const ulonglong2*)&wrow[(ky * 3 + kx) * 4 + 2];
#pragma unroll
            for (int dx = 0; dx < 2; dx++) {
                ull pt = top[dx + kx];
                ull pb = bot[dx + kx];
                fma2(acc[dx][0], wa.x, pt);
                fma2(acc[dx][1], wa.y, pt);
                fma2(acc[dx][2], wb.x, pt);
                fma2(acc[dx][3], wb.y, pt);
                fma2(acc[2 + dx][0], wa.x, pb);
                fma2(acc[2 + dx][1], wa.y, pb);
                fma2(acc[2 + dx][2], wb.x, pb);
                fma2(acc[2 + dx][3], wb.y, pb);
            }
        }
    }
}

// ---------------------------------------------------------------------------
// SINGLE FUSED KERNEL, warp-autonomous: 128-thread blocks; each of the 4
// warps owns an 8x4 pooled sub-tile and runs conv1->conv2 privately.
// ONE block barrier per tile (after the cooperative cAt fill); all other
// sync is __syncwarp. grid (4, 8, 96).
// ---------------------------------------------------------------------------
__global__ void __launch_bounds__(128, 8) fused_kernel(
    const float* __restrict__ x,
    const float* __restrict__ w1, const float* __restrict__ b1,
    const float* __restrict__ w2, const float* __restrict__ b2,
    const float* __restrict__ w3, const float* __restrict__ b3,
    float* __restrict__ low, float* __restrict__ high)
{
    __shared__ __align__(16) float cAt[38][72];          // 10.9 KB (block-shared)
    __shared__ __align__(16) float s1t[4][4][10][24];    // 15.4 KB (warp-private)
    __shared__ __align__(16) ull    w2p[16 * 9 * 4];     //  4.6 KB
    __shared__ __align__(16) ull    w1p[8 * 10];         //  640 B
    __shared__ float2 b1p[8];
    __shared__ float  b2s[8];
    __shared__ float  w3s[32];
    __shared__ float  b3s[4];

    const int tid  = threadIdx.y * 16 + threadIdx.x;
    const int lane = tid & 31;
    const int wid  = tid >> 5;
    const int wx = wid & 1,  wy = wid >> 1;      // warp grid 2x2
    const int lx = lane & 7, ly = lane >> 3;     // lane grid 8x4
    const int px0 = blockIdx.x * 16;             // pooled-64 col origin
    const int py0 = blockIdx.y * 8;              // pooled-64 row origin
    const int img = blockIdx.z;

    // ---- weights to smem ----
    if (tid < 80) {
        int icp = tid / 10, k = tid - 10 * icp;
        w1p[tid] = (k < 9) ? pk2(w1[(2 * icp) * 9 + k], w1[(2 * icp + 1) * 9 + k]) : 0ull;
    }
    if (tid < 8)  b1p[tid] = make_float2(b1[2 * tid], b1[2 * tid + 1]);
    if (tid < 8)  b2s[tid] = b2[tid];
    if (tid < 32) w3s[tid] = w3[tid];
    if (tid < 4)  b3s[tid] = b3[tid];
    for (int idx = tid; idx < 16 * 9 * 4; idx += 128) {
        int ocp = idx & 3;
        int k   = (idx >> 2) % 9;
        int ic  = idx / 36;
        int oc0 = 2 * ocp;
        float lo = w2[(oc0 * 16 + ic) * 9 + k];
        float hi = w2[((oc0 + 1) * 16 + ic) * 9 + k];
        w2p[idx] = pk2(lo, hi);
    }

    // ---- DWT fill: cA 38x70 tile from x; cH/cV for owned 64x32 -> high ----
    {
        const float* xin = x + (size_t)img * HH * WW;
        float* hp = high + (size_t)img * (2 * HS * WS);
        const int gr0 = 4 * py0 - 3, gc0 = 4 * px0 - 3;  // cA-space origin
        int r = tid / 70, c = tid - 70 * (tid / 70);
        for (int k = tid; k < 38 * 70; k += 128) {
            int ir = gr0 + r, ic = gc0 + c;              // cA coords
            float va = 0.f, vh = 0.f, vv = 0.f;
            if ((unsigned)ir < (unsigned)HS && (unsigned)ic < (unsigned)WS) {
                const float* p0 = xin + (size_t)(2 * ir) * WW + 2 * ic;
                float2 q0 = *(const float2*)p0;
                float2 q1 = *(const float2*)(p0 + WW);
                float s0 = q0.x + q0.y, s1 = q1.x + q1.y;
                float e0 = q0.x - q0.y, e1 = q1.x - q1.y;
                va = 0.5f * (s0 + s1);
                vh = 0.5f * (s0 - s1);
                vv = 0.5f * (e0 + e1);
            }
            cAt[r][c] = va;
            if (r >= 3 && r < 35 && c >= 3 && c < 67) {  // owned region only
                int o = ir * WS + ic;
                hp[o] = vh;
                hp[HS * WS + o] = vv;
            }
            c += 58; r += 1;                 // advance 128 = 1*70 + 58
            if (c >= 70) { c -= 70; r++; }
        }
    }
    __syncthreads();   // the ONLY block barrier: cAt ready for all warps

    const int r0s = 2 * py0 - 1, c0s = 2 * px0 - 1;  // s1 global origin
    const bool interior = (py0 >= 8 && py0 <= 48) && (px0 == 16 || px0 == 32);

    float (*s1w)[10][24] = s1t[wid];   // this warp's 4 private buffers

    ull acc[4][4];
#pragma unroll
    for (int q = 0; q < 4; q++)
#pragma unroll
        for (int p = 0; p < 4; p++) acc[q][p] = 0ull;

    for (int rnd = 0; rnd < 4; rnd++) {
        conv1_pair_w(cAt, s1w[0], s1w[1], &w1p[(2 * rnd) * 10],     b1p[2 * rnd],
                     lane, wx, wy, r0s, c0s, interior);
        conv1_pair_w(cAt, s1w[2], s1w[3], &w1p[(2 * rnd + 1) * 10], b1p[2 * rnd + 1],
                     lane, wx, wy, r0s, c0s, interior);
        __syncwarp();
#pragma unroll
        for (int j = 0; j < 4; j++)
            conv2_stage_w((const float(*)[24])s1w[j], &w2p[(4 * rnd + j) * 36],
                          lx, ly, acc);
        __syncwarp();   // buffers free for next round's conv1 overwrite
    }

    // ---- epilogue: bias + pool-max + relu, then 1x1 conv3 ----
    float r8[8];
#pragma unroll
    for (int p = 0; p < 4; p++) {
        float lo0, hi0, lo1, hi1, lo2, hi2, lo3, hi3;
        upk2(acc[0][p], lo0, hi0);
        upk2(acc[1][p], lo1, hi1);
        upk2(acc[2][p], lo2, hi2);
        upk2(acc[3][p], lo3, hi3);
        float mlo = fmaxf(fmaxf(lo0, lo1), fmaxf(lo2, lo3));
        float mhi = fmaxf(fmaxf(hi0, hi1), fmaxf(hi2, hi3));
        r8[2 * p]     = fmaxf(mlo + b2s[2 * p], 0.f);
        r8[2 * p + 1] = fmaxf(mhi + b2s[2 * p + 1], 0.f);
    }

    const int oy = py0 + 4 * wy + ly, ox = px0 + 8 * wx + lx;
    const int pix = oy * 64 + ox;
    float* lp = low + (size_t)img * 4 * 4096 + pix;
#pragma unroll
    for (int oc = 0; oc < 4; oc++) {
        float s = b3s[oc];
#pragma unroll
        for (int ic = 0; ic < 8; ic++) s = fmaf(w3s[oc * 8 + ic], r8[ic], s);
        lp[oc * 4096] = s;
    }
}

// ---------------------------------------------------------------------------
extern "C" void kernel_launch(void* const* d_in, const int* in_sizes, int n_in,
                              void* d_out, int out_size) {
    const float* x  = (const float*)d_in[0];
    const float* w1 = (const float*)d_in[1];
    const float* b1 = (const float*)d_in[2];
    const float* w2 = (const float*)d_in[3];
    const float* b2 = (const float*)d_in[4];
    const float* w3 = (const float*)d_in[5];
    const float* b3 = (const float*)d_in[6];

    float* out  = (float*)d_out;
    float* low  = out;                    // 96*4*64*64 = 1,572,864 floats
    float* high = out + 1572864;          // 96*2*256*256 = 12,582,912 floats

    fused_kernel<<<dim3(4, 8, NIMG), dim3(16, 8)>>>(x, w1, b1, w2, b2, w3, b3, low, high);
}

// round 15
// speedup vs baseline: 1.1569x; 1.1569x over previous
#include <cuda_runtime.h>

#define NIMG 96
#define HH 512
#define WW 512
#define HS 256   // cA resolution
#define WS 256

typedef unsigned long long ull;

// Constant-memory packed weights. Layout (ull indices):
//   [0..575]   W2P: [(ic*9 + k)*4 + ocp] = pk2(w2[oc0][ic][k], w2[oc0+1][ic][k])
//   [576..655] W1P: 8 chpairs x stride 10; pk2(w1[2p][k], w1[2p+1][k])
//   [656..663] B1P: pk2(b1[2i], b1[2i+1])
//   [664..667] B2P: pk2(b2[2p], b2[2p+1])
//   [668..683] W3P: pk2(w3flat[2i], w3flat[2i+1])
//   [684..685] B3P: pk2(b3[2i], b3[2i+1])
#define PK_TOTAL 686
__constant__ ull c_pack[PK_TOTAL];
__device__   ull g_pack[PK_TOTAL];

__device__ __forceinline__ ull pk2(float lo, float hi) {
    ull r; asm("mov.b64 %0, {%1, %2};" : "=l"(r) : "f"(lo), "f"(hi)); return r;
}
__device__ __forceinline__ void upk2(ull v, float& lo, float& hi) {
    asm("mov.b64 {%0, %1}, %2;" : "=f"(lo), "=f"(hi) : "l"(v));
}
__device__ __forceinline__ void fma2(ull& d, ull a, ull b) {
    asm("fma.rn.f32x2 %0, %1, %2, %0;" : "+l"(d) : "l"(a), "l"(b));
}

// ---------------------------------------------------------------------------
// Prep kernel: pack weights into staging buffer (then memcpy'd to c_pack).
// ---------------------------------------------------------------------------
__global__ void prep_kernel(
    const float* __restrict__ w1, const float* __restrict__ b1,
    const float* __restrict__ w2, const float* __restrict__ b2,
    const float* __restrict__ w3, const float* __restrict__ b3)
{
    int tid = threadIdx.x;
    for (int idx = tid; idx < 576; idx += 128) {
        int ocp = idx & 3;
        int k   = (idx >> 2) % 9;
        int ic  = idx / 36;
        int oc0 = 2 * ocp;
        g_pack[idx] = pk2(w2[(oc0 * 16 + ic) * 9 + k], w2[((oc0 + 1) * 16 + ic) * 9 + k]);
    }
    if (tid < 80) {
        int icp = tid / 10, k = tid - 10 * icp;
        g_pack[576 + tid] = (k < 9) ? pk2(w1[(2 * icp) * 9 + k], w1[(2 * icp + 1) * 9 + k]) : 0ull;
    }
    if (tid < 8)  g_pack[656 + tid] = pk2(b1[2 * tid], b1[2 * tid + 1]);
    if (tid < 4)  g_pack[664 + tid] = pk2(b2[2 * tid], b2[2 * tid + 1]);
    if (tid < 16) g_pack[668 + tid] = pk2(w3[2 * tid], w3[2 * tid + 1]);
    if (tid < 2)  g_pack[684 + tid] = pk2(b3[2 * tid], b3[2 * tid + 1]);
}

// ---------------------------------------------------------------------------
// conv1 pair stage, 2-WIDE (R12 structure): two adjacent pooled outputs x two
// channels (f32x2 lanes) per task from a 4x6 strip. 18x17 tasks / 128 thr.
// Weights from __constant__ (uniform LDC — off the smem port).
// ---------------------------------------------------------------------------
__device__ __forceinline__ void conv1_pair(
    const float (*cAt)[72], float (*d0)[36], float (*d1)[36],
    int wbase, float2 bias2, int t0,
    int r0s, int c0s, bool interior)
{
    ull wq[9];
#pragma unroll
    for (int k = 0; k < 9; k++) wq[k] = c_pack[wbase + k];

    int r = t0 / 17, cp = t0 - 17 * r;
    for (int k = t0; k < 18 * 17; k += 128) {
        const float* base = &cAt[2 * r][4 * cp];   // 16B aligned

        ull a[2][4];
#pragma unroll
        for (int j = 0; j < 2; j++)
#pragma unroll
            for (int q = 0; q < 4; q++) a[j][q] = 0ull;

#pragma unroll
        for (int i = 0; i < 4; i++) {              // input row 2r + i
            float4 q0 = *(const float4*)(base + i * 72);
            float2 q1 = *(const float2*)(base + i * 72 + 4);
            ull bb[6];
            bb[0] = pk2(q0.x, q0.x); bb[1] = pk2(q0.y, q0.y);
            bb[2] = pk2(q0.z, q0.z); bb[3] = pk2(q0.w, q0.w);
            bb[4] = pk2(q1.x, q1.x); bb[5] = pk2(q1.y, q1.y);
            if (i < 3) {                            // ky = i -> dy = 0
#pragma unroll
                for (int kx = 0; kx < 3; kx++) {
                    ull w = wq[3 * i + kx];
                    fma2(a[0][0], w, bb[kx]);
                    fma2(a[0][1], w, bb[kx + 1]);
                    fma2(a[1][0], w, bb[kx + 2]);
                    fma2(a[1][1], w, bb[kx + 3]);
                }
            }
            if (i > 0) {                            // ky = i-1 -> dy = 1
#pragma unroll
                for (int kx = 0; kx < 3; kx++) {
                    ull w = wq[3 * (i - 1) + kx];
                    fma2(a[0][2], w, bb[kx]);
                    fma2(a[0][3], w, bb[kx + 1]);
                    fma2(a[1][2], w, bb[kx + 2]);
                    fma2(a[1][3], w, bb[kx + 3]);
                }
            }
        }

        float2 o0, o1;
#pragma unroll
        for (int j = 0; j < 2; j++) {
            float l0, h0, l1, h1, l2, h2, l3, h3;
            upk2(a[j][0], l0, h0); upk2(a[j][1], l1, h1);
            upk2(a[j][2], l2, h2); upk2(a[j][3], l3, h3);
            float m0 = fmaxf(fmaxf(l0, l1), fmaxf(l2, l3));
            float m1 = fmaxf(fmaxf(h0, h1), fmaxf(h2, h3));
            m0 = fmaxf(m0 + bias2.x, 0.f);   // max(relu(x+b)) == relu(max+b)
            m1 = fmaxf(m1 + bias2.y, 0.f);
            if (!interior) {
                int rs = r0s + r, cs = c0s + 2 * cp + j;
                if ((unsigned)rs >= 128u || (unsigned)cs >= 128u) { m0 = 0.f; m1 = 0.f; }
            }
            ((float*)&o0)[j] = m0;
            ((float*)&o1)[j] = m1;
        }
        *(float2*)&d0[r][2 * cp] = o0;
        *(float2*)&d1[r][2 * cp] = o1;

        cp += 9; r += 7;                 // advance 128 = 7*17 + 9
        if (cp >= 17) { cp -= 17; r++; }
    }
}

// ---------------------------------------------------------------------------
// conv2 stage (R12 structure): rolling 2-row broadcast buffer; oc-pairs in
// f32x2 lanes. Weights from __constant__ (uniform LDC, vector) — this removes
// the single largest smem-port consumer (18 LDS.128 per stage).
// ---------------------------------------------------------------------------
__device__ __forceinline__ void conv2_stage(
    const float (*src)[36], int wb,
    int tx, int ty, ull acc[4][4])
{
    ull rA[4], rB[4];
    {
        float2 v0 = *(const float2*)&src[2 * ty][2 * tx];
        float2 v1 = *(const float2*)&src[2 * ty][2 * tx + 2];
        rA[0] = pk2(v0.x, v0.x); rA[1] = pk2(v0.y, v0.y);
        rA[2] = pk2(v1.x, v1.x); rA[3] = pk2(v1.y, v1.y);
    }
#pragma unroll
    for (int ky = 0; ky < 3; ky++) {
        ull* top = (ky & 1) ? rB : rA;
        ull* bot = (ky & 1) ? rA : rB;
        {
            float2 v0 = *(const float2*)&src[2 * ty + ky + 1][2 * tx];
            float2 v1 = *(const float2*)&src[2 * ty + ky + 1][2 * tx + 2];
            bot[0] = pk2(v0.x, v0.x); bot[1] = pk2(v0.y, v0.y);
            bot[2] = pk2(v1.x, v1.x); bot[3] = pk2(v1.y, v1.y);
        }
#pragma unroll
        for (int kx = 0; kx < 3; kx++) {
            ull w0 = c_pack[wb + (ky * 3 + kx) * 4 + 0];
            ull w1 = c_pack[wb + (ky * 3 + kx) * 4 + 1];
            ull w2 = c_pack[wb + (ky * 3 + kx) * 4 + 2];
            ull w3 = c_pack[wb + (ky * 3 + kx) * 4 + 3];
#pragma unroll
            for (int dx = 0; dx < 2; dx++) {
                ull pt = top[dx + kx];
                ull pb = bot[dx + kx];
                fma2(acc[dx][0], w0, pt);
                fma2(acc[dx][1], w1, pt);
                fma2(acc[dx][2], w2, pt);
                fma2(acc[dx][3], w3, pt);
                fma2(acc[2 + dx][0], w0, pb);
                fma2(acc[2 + dx][1], w1, pb);
                fma2(acc[2 + dx][2], w2, pb);
                fma2(acc[2 + dx][3], w3, pb);
            }
        }
    }
}

// ---------------------------------------------------------------------------
// FUSED KERNEL (R12 geometry): 128-thread blocks (16x8 pooled tile), 8/SM.
// Haar DWT fill -> conv1+relu+pool -> conv2+relu+pool -> conv3(1x1).
// smem holds ONLY data tiles (weights in constant). grid (4, 8, 96).
// ---------------------------------------------------------------------------
__global__ void __launch_bounds__(128, 8) fused_kernel(
    const float* __restrict__ x,
    float* __restrict__ low, float* __restrict__ high)
{
    __shared__ __align__(16) float cAt[38][72];      // 10.9 KB
    __shared__ __align__(16) float s1t[4][18][36];   // 10.4 KB

    const int tx = threadIdx.x, ty = threadIdx.y;    // block (16, 8)
    const int tid = ty * 16 + tx;
    const int px0 = blockIdx.x * 16;                 // pooled-64 col origin
    const int py0 = blockIdx.y * 8;                  // pooled-64 row origin
    const int img = blockIdx.z;

    // ---- DWT fill: cA 38x70 tile from x; cH/cV for owned 64x32 -> high ----
    {
        const float* xin = x + (size_t)img * HH * WW;
        float* hp = high + (size_t)img * (2 * HS * WS);
        const int gr0 = 4 * py0 - 3, gc0 = 4 * px0 - 3;  // cA-space origin
        int r = tid / 70, c = tid - 70 * (tid / 70);
        for (int k = tid; k < 38 * 70; k += 128) {
            int ir = gr0 + r, ic = gc0 + c;              // cA coords
            float va = 0.f, vh = 0.f, vv = 0.f;
            if ((unsigned)ir < (unsigned)HS && (unsigned)ic < (unsigned)WS) {
                const float* p0 = xin + (size_t)(2 * ir) * WW + 2 * ic;
                float2 q0 = *(const float2*)p0;
                float2 q1 = *(const float2*)(p0 + WW);
                float s0 = q0.x + q0.y, s1 = q1.x + q1.y;
                float e0 = q0.x - q0.y, e1 = q1.x - q1.y;
                va = 0.5f * (s0 + s1);
                vh = 0.5f * (s0 - s1);
                vv = 0.5f * (e0 + e1);
            }
            cAt[r][c] = va;
            if (r >= 3 && r < 35 && c >= 3 && c < 67) {  // owned region only
                int o = ir * WS + ic;
                hp[o] = vh;
                hp[HS * WS + o] = vv;
            }
            c += 58; r += 1;                 // advance 128 = 1*70 + 58
            if (c >= 70) { c -= 70; r++; }
        }
    }

    const int r0s = 2 * py0 - 1, c0s = 2 * px0 - 1;  // s1-tile global origin
    const bool interior = (py0 >= 8 && py0 <= 48) && (px0 == 16 || px0 == 32);

    ull acc[4][4];
#pragma unroll
    for (int q = 0; q < 4; q++)
#pragma unroll
        for (int p = 0; p < 4; p++) acc[q][p] = 0ull;

    for (int rnd = 0; rnd < 4; rnd++) {
        __syncthreads();   // orders fill->conv1 (rnd 0) and s1t reuse
        const int tA = (tid + rnd * 32) & 127;            // rotate task starts
        const int tB = (tid + rnd * 32 + 64) & 127;
        float bx, by;
        upk2(c_pack[656 + 2 * rnd], bx, by);
        conv1_pair((const float(*)[72])cAt, s1t[0], s1t[1],
                   576 + (2 * rnd) * 10,     make_float2(bx, by), tA, r0s, c0s, interior);
        upk2(c_pack[656 + 2 * rnd + 1], bx, by);
        conv1_pair((const float(*)[72])cAt, s1t[2], s1t[3],
                   576 + (2 * rnd + 1) * 10, make_float2(bx, by), tB, r0s, c0s, interior);
        __syncthreads();
#pragma unroll
        for (int j = 0; j < 4; j++)
            conv2_stage((const float(*)[36])s1t[j], (4 * rnd + j) * 36, tx, ty, acc);
    }

    // ---- epilogue: bias + pool-max + relu, then 1x1 conv3 ----
    float r8[8];
#pragma unroll
    for (int p = 0; p < 4; p++) {
        float b2lo, b2hi;
        upk2(c_pack[664 + p], b2lo, b2hi);
        float lo0, hi0, lo1, hi1, lo2, hi2, lo3, hi3;
        upk2(acc[0][p], lo0, hi0);
        upk2(acc[1][p], lo1, hi1);
        upk2(acc[2][p], lo2, hi2);
        upk2(acc[3][p], lo3, hi3);
        float mlo = fmaxf(fmaxf(lo0, lo1), fmaxf(lo2, lo3));
        float mhi = fmaxf(fmaxf(hi0, hi1), fmaxf(hi2, hi3));
        r8[2 * p]     = fmaxf(mlo + b2lo, 0.f);
        r8[2 * p + 1] = fmaxf(mhi + b2hi, 0.f);
    }

    float b3v[4];
    upk2(c_pack[684], b3v[0], b3v[1]);
    upk2(c_pack[685], b3v[2], b3v[3]);

    const int pix = (py0 + ty) * 64 + px0 + tx;
    float* lp = low + (size_t)img * 4 * 4096 + pix;
#pragma unroll
    for (int oc = 0; oc < 4; oc++) {
        float s = b3v[oc];
#pragma unroll
        for (int icp = 0; icp < 4; icp++) {
            float wlo, whi;
            upk2(c_pack[668 + oc * 4 + icp], wlo, whi);
            s = fmaf(wlo, r8[2 * icp], s);
            s = fmaf(whi, r8[2 * icp + 1], s);
        }
        lp[oc * 4096] = s;
    }
}

// ---------------------------------------------------------------------------
extern "C" void kernel_launch(void* const* d_in, const int* in_sizes, int n_in,
                              void* d_out, int out_size) {
    const float* x  = (const float*)d_in[0];
    const float* w1 = (const float*)d_in[1];
    const float* b1 = (const float*)d_in[2];
    const float* w2 = (const float*)d_in[3];
    const float* b2 = (const float*)d_in[4];
    const float* w3 = (const float*)d_in[5];
    const float* b3 = (const float*)d_in[6];

    float* out  = (float*)d_out;
    float* low  = out;                    // 96*4*64*64 = 1,572,864 floats
    float* high = out + 1572864;          // 96*2*256*256 = 12,582,912 floats

    // pack weights (device) -> copy into __constant__ (D2D, graph-capturable)
    prep_kernel<<<1, 128>>>(w1, b1, w2, b2, w3, b3);
    void* gaddr = nullptr;
    cudaGetSymbolAddress(&gaddr, g_pack);
    cudaMemcpyToSymbolAsync(c_pack, gaddr, PK_TOTAL * sizeof(ull), 0,
                            cudaMemcpyDeviceToDevice, 0);

    fused_kernel<<<dim3(4, 8, NIMG), dim3(16, 8)>>>(x, low, high);
}